// round 1
// baseline (speedup 1.0000x reference)
#include <cuda_runtime.h>
#include <cstdint>

// ---------------------------------------------------------------------------
// Relative attention (ViT-style) — fp32 baseline, structured for later
// tensor-core / flash-fusion rounds.
//
// Shapes: x[32,577,512], qkv_w[1536,512], proj_w[512,512], proj_b[512],
//         bias_table[2209,8], rel_index[577,577] (int32), out[32,577,512].
// ---------------------------------------------------------------------------

namespace {
constexpr int BATCH = 32;
constexpr int NH    = 8;
constexpr int NTOK  = 577;
constexpr int DIM   = 512;
constexpr int DH    = 64;
constexpr int BH    = BATCH * NH;        // 256
constexpr int MROWS = BATCH * NTOK;      // 18464
constexpr int NN    = NTOK * NTOK;       // 332929
constexpr float SCALE = 0.125f;          // 64^-0.5
}

// Scratch (device globals: allocation-free contract)
__device__ float g_q[BH * NTOK * DH];        // 37.8 MB
__device__ float g_k[BH * NTOK * DH];
__device__ float g_v[BH * NTOK * DH];
__device__ float g_bias[NH * NN];            // 10.6 MB
__device__ float g_s[BH * NN];               // 341 MB (scores / probs)
__device__ float g_attn[MROWS * DIM];        // 37.8 MB

// ---------------------------------------------------------------------------
// Bias gather: g_bias[h][n][m] = table[rel[n][m]][h]
// ---------------------------------------------------------------------------
__global__ void bias_expand(const float* __restrict__ table,
                            const int* __restrict__ rel) {
    int idx = blockIdx.x * 256 + threadIdx.x;
    if (idx >= NN) return;
    int r = rel[idx];
#pragma unroll
    for (int h = 0; h < NH; ++h)
        g_bias[h * NN + idx] = table[r * NH + h];
}

// ---------------------------------------------------------------------------
// NT SGEMM: C[m,n] = sum_k A[m,k] * Bm[n,k], K = 512 fixed.
// MODE 0: A = x, Bm = qkv_w (Ntot=1536); scatter epilogue into g_q/g_k/g_v.
// MODE 1: A = g_attn, Bm = proj_w (Ntot=512); epilogue adds proj_b -> Cout.
// 128x128x16 tile, 256 threads, 8x8 per-thread microtile.
// ---------------------------------------------------------------------------
template <int MODE>
__global__ __launch_bounds__(256) void sgemm_nt(const float* __restrict__ Ain,
                                                const float* __restrict__ Bm,
                                                const float* __restrict__ bias,
                                                float* __restrict__ Cout,
                                                int Ntot) {
    const float* A = (MODE == 1) ? g_attn : Ain;
    __shared__ float As[16][132];
    __shared__ float Bs[16][132];
    const int tid = threadIdx.x;
    const int m0 = blockIdx.y * 128;
    const int n0 = blockIdx.x * 128;
    const int rm = (tid >> 4) * 8;
    const int rn = (tid & 15) * 8;

    float acc[8][8];
#pragma unroll
    for (int i = 0; i < 8; ++i)
#pragma unroll
        for (int j = 0; j < 8; ++j) acc[i][j] = 0.f;

    for (int k0 = 0; k0 < DIM; k0 += 16) {
#pragma unroll
        for (int it = 0; it < 2; ++it) {
            int vi = tid + it * 256;          // 0..511
            int row = vi >> 2;                // 0..127
            int c4 = (vi & 3) << 2;           // 0,4,8,12
            int gm = m0 + row;
            float4 va = make_float4(0.f, 0.f, 0.f, 0.f);
            if (gm < MROWS)
                va = *reinterpret_cast<const float4*>(A + (size_t)gm * DIM + k0 + c4);
            As[c4 + 0][row] = va.x; As[c4 + 1][row] = va.y;
            As[c4 + 2][row] = va.z; As[c4 + 3][row] = va.w;
            int gn = n0 + row;
            float4 vb = make_float4(0.f, 0.f, 0.f, 0.f);
            if (gn < Ntot)
                vb = *reinterpret_cast<const float4*>(Bm + (size_t)gn * DIM + k0 + c4);
            Bs[c4 + 0][row] = vb.x; Bs[c4 + 1][row] = vb.y;
            Bs[c4 + 2][row] = vb.z; Bs[c4 + 3][row] = vb.w;
        }
        __syncthreads();
#pragma unroll
        for (int kk = 0; kk < 16; ++kk) {
            float a[8], b[8];
            *reinterpret_cast<float4*>(a)     = *reinterpret_cast<const float4*>(&As[kk][rm]);
            *reinterpret_cast<float4*>(a + 4) = *reinterpret_cast<const float4*>(&As[kk][rm + 4]);
            *reinterpret_cast<float4*>(b)     = *reinterpret_cast<const float4*>(&Bs[kk][rn]);
            *reinterpret_cast<float4*>(b + 4) = *reinterpret_cast<const float4*>(&Bs[kk][rn + 4]);
#pragma unroll
            for (int i = 0; i < 8; ++i)
#pragma unroll
                for (int j = 0; j < 8; ++j) acc[i][j] += a[i] * b[j];
        }
        __syncthreads();
    }

    if (MODE == 0) {
#pragma unroll
        for (int i = 0; i < 8; ++i) {
            int gm = m0 + rm + i;
            if (gm < MROWS) {
                int b_ = gm / NTOK;
                int n_ = gm - b_ * NTOK;
#pragma unroll
                for (int j = 0; j < 8; ++j) {
                    int gn = n0 + rn + j;     // < 1536 always (grid exact)
                    int part = gn >> 9;
                    int rem = gn & 511;
                    int h_ = rem >> 6;
                    int dd = rem & 63;
                    float* dst = (part == 0) ? g_q : (part == 1) ? g_k : g_v;
                    dst[((b_ * NH + h_) * NTOK + n_) * DH + dd] = acc[i][j];
                }
            }
        }
    } else {
#pragma unroll
        for (int i = 0; i < 8; ++i) {
            int gm = m0 + rm + i;
            if (gm < MROWS) {
#pragma unroll
                for (int j = 0; j < 8; ++j) {
                    int gn = n0 + rn + j;     // < 512 always (grid exact)
                    Cout[(size_t)gm * DIM + gn] = acc[i][j] + bias[gn];
                }
            }
        }
    }
}

// ---------------------------------------------------------------------------
// Scores: S[bh][n][m] = SCALE * dot(q[bh][n], k[bh][m]) + bias[h][n][m]
// One 64x64 tile per block; d=64 fits entirely in smem (single K pass).
// ---------------------------------------------------------------------------
__global__ __launch_bounds__(256) void attn_scores() {
    __shared__ float Qt[DH][68];   // [kd][row], padded for alignment
    __shared__ float Kt[DH][68];
    const int bh = blockIdx.z;
    const int qt = blockIdx.y;
    const int kt = blockIdx.x;
    const int tid = threadIdx.x;
    const float* qbase = g_q + (size_t)bh * NTOK * DH;
    const float* kbase = g_k + (size_t)bh * NTOK * DH;

#pragma unroll
    for (int it = 0; it < 4; ++it) {
        int vi = tid + it * 256;      // 0..1023
        int row = vi >> 4;            // 0..63
        int c4 = (vi & 15) << 2;      // 0..60
        int gq = qt * 64 + row;
        float4 v = make_float4(0.f, 0.f, 0.f, 0.f);
        if (gq < NTOK) v = *reinterpret_cast<const float4*>(qbase + gq * DH + c4);
        Qt[c4 + 0][row] = v.x; Qt[c4 + 1][row] = v.y;
        Qt[c4 + 2][row] = v.z; Qt[c4 + 3][row] = v.w;
        int gk = kt * 64 + row;
        float4 w = make_float4(0.f, 0.f, 0.f, 0.f);
        if (gk < NTOK) w = *reinterpret_cast<const float4*>(kbase + gk * DH + c4);
        Kt[c4 + 0][row] = w.x; Kt[c4 + 1][row] = w.y;
        Kt[c4 + 2][row] = w.z; Kt[c4 + 3][row] = w.w;
    }
    __syncthreads();

    const int r0 = (tid >> 4) << 2;
    const int c0 = (tid & 15) << 2;
    float acc[4][4];
#pragma unroll
    for (int i = 0; i < 4; ++i)
#pragma unroll
        for (int j = 0; j < 4; ++j) acc[i][j] = 0.f;

#pragma unroll 8
    for (int kd = 0; kd < DH; ++kd) {
        float a[4], b[4];
        *reinterpret_cast<float4*>(a) = *reinterpret_cast<const float4*>(&Qt[kd][r0]);
        *reinterpret_cast<float4*>(b) = *reinterpret_cast<const float4*>(&Kt[kd][c0]);
#pragma unroll
        for (int i = 0; i < 4; ++i)
#pragma unroll
            for (int j = 0; j < 4; ++j) acc[i][j] += a[i] * b[j];
    }

    const int h_ = bh & 7;
    float* srow = g_s + (size_t)bh * NN;
    const float* brow = g_bias + (size_t)h_ * NN;
#pragma unroll
    for (int i = 0; i < 4; ++i) {
        int gq = qt * 64 + r0 + i;
        if (gq < NTOK) {
            int off = gq * NTOK;
#pragma unroll
            for (int j = 0; j < 4; ++j) {
                int gk = kt * 64 + c0 + j;
                if (gk < NTOK)
                    srow[off + gk] = acc[i][j] * SCALE + brow[off + gk];
            }
        }
    }
}

// ---------------------------------------------------------------------------
// Row softmax in-place over g_s. One 128-thread block per (bh, row).
// ---------------------------------------------------------------------------
__global__ __launch_bounds__(128) void softmax_rows() {
    const int rowid = blockIdx.x;
    const int bh = rowid / NTOK;
    const int r = rowid - bh * NTOK;
    float* row = g_s + (size_t)bh * NN + (size_t)r * NTOK;
    const int t = threadIdx.x;

    float v[5];
    float m = -1e30f;
#pragma unroll
    for (int i = 0; i < 5; ++i) {
        int idx = t + i * 128;
        v[i] = (idx < NTOK) ? row[idx] : -1e30f;
        m = fmaxf(m, v[i]);
    }
#pragma unroll
    for (int o = 16; o > 0; o >>= 1) m = fmaxf(m, __shfl_xor_sync(0xFFFFFFFFu, m, o));
    __shared__ float red[4];
    if ((t & 31) == 0) red[t >> 5] = m;
    __syncthreads();
    m = fmaxf(fmaxf(red[0], red[1]), fmaxf(red[2], red[3]));
    __syncthreads();

    float s = 0.f;
#pragma unroll
    for (int i = 0; i < 5; ++i) {
        v[i] = __expf(v[i] - m);   // invalid lanes: exp(-huge) = 0
        s += v[i];
    }
#pragma unroll
    for (int o = 16; o > 0; o >>= 1) s += __shfl_xor_sync(0xFFFFFFFFu, s, o);
    if ((t & 31) == 0) red[t >> 5] = s;
    __syncthreads();
    s = red[0] + red[1] + red[2] + red[3];
    const float inv = 1.f / s;
#pragma unroll
    for (int i = 0; i < 5; ++i) {
        int idx = t + i * 128;
        if (idx < NTOK) row[idx] = v[i] * inv;
    }
}

// ---------------------------------------------------------------------------
// PV: O[bh][n][dd] = sum_m P[bh][n][m] * V[bh][m][dd]
// Writes g_attn in [b][n][h*64+dd] layout (ready for output projection).
// ---------------------------------------------------------------------------
__global__ __launch_bounds__(256) void attn_pv() {
    __shared__ float Pt[64][68];   // [m_local][q_row]
    __shared__ float Vs[64][64];   // [m_local][dd]
    const int bh = blockIdx.y;
    const int qt = blockIdx.x;
    const int tid = threadIdx.x;
    const float* srow = g_s + (size_t)bh * NN;
    const float* vbase = g_v + (size_t)bh * NTOK * DH;
    const int r0 = (tid >> 4) << 2;
    const int c0 = (tid & 15) << 2;

    float acc[4][4];
#pragma unroll
    for (int i = 0; i < 4; ++i)
#pragma unroll
        for (int j = 0; j < 4; ++j) acc[i][j] = 0.f;

    for (int mt = 0; mt < 10; ++mt) {
        const int m0c = mt * 64;
#pragma unroll
        for (int it = 0; it < 4; ++it) {
            int vi = tid + it * 256;
            int row = vi >> 4;          // 0..63
            int c4 = (vi & 15) << 2;    // 0..60
            int gq = qt * 64 + row;
            // P chunk (rows unaligned: 577-stride) -> scalar loads, transpose
#pragma unroll
            for (int j = 0; j < 4; ++j) {
                int gm = m0c + c4 + j;
                float pv = 0.f;
                if (gq < NTOK && gm < NTOK) pv = srow[(size_t)gq * NTOK + gm];
                Pt[c4 + j][row] = pv;
            }
            // V chunk (64-stride, aligned) -> vector load, natural layout
            int gm2 = m0c + row;
            float4 vv = make_float4(0.f, 0.f, 0.f, 0.f);
            if (gm2 < NTOK) vv = *reinterpret_cast<const float4*>(vbase + gm2 * DH + c4);
            *reinterpret_cast<float4*>(&Vs[row][c4]) = vv;
        }
        __syncthreads();
#pragma unroll 8
        for (int mm = 0; mm < 64; ++mm) {
            float a[4], b[4];
            *reinterpret_cast<float4*>(a) = *reinterpret_cast<const float4*>(&Pt[mm][r0]);
            *reinterpret_cast<float4*>(b) = *reinterpret_cast<const float4*>(&Vs[mm][c0]);
#pragma unroll
            for (int i = 0; i < 4; ++i)
#pragma unroll
                for (int j = 0; j < 4; ++j) acc[i][j] += a[i] * b[j];
        }
        __syncthreads();
    }

    const int b_ = bh >> 3;
    const int h_ = bh & 7;
#pragma unroll
    for (int i = 0; i < 4; ++i) {
        int gq = qt * 64 + r0 + i;
        if (gq < NTOK) {
#pragma unroll
            for (int j = 0; j < 4; ++j)
                g_attn[((size_t)(b_ * NTOK + gq)) * DIM + h_ * DH + c0 + j] = acc[i][j];
        }
    }
}

// ---------------------------------------------------------------------------
// Launch
// ---------------------------------------------------------------------------
extern "C" void kernel_launch(void* const* d_in, const int* in_sizes, int n_in,
                              void* d_out, int out_size) {
    (void)in_sizes; (void)n_in; (void)out_size;
    const float* x          = (const float*)d_in[0];
    const float* qkv_w      = (const float*)d_in[1];
    const float* proj_w     = (const float*)d_in[2];
    const float* proj_b     = (const float*)d_in[3];
    const float* bias_table = (const float*)d_in[4];
    const int*   rel_index  = (const int*)d_in[5];
    float* out = (float*)d_out;

    // 1. expand relative-position bias to [H][N][N]
    bias_expand<<<(NN + 255) / 256, 256>>>(bias_table, rel_index);

    // 2. QKV projection (M=18464, N=1536, K=512), scatter to q/k/v
    sgemm_nt<0><<<dim3(12, 145), 256>>>(x, qkv_w, nullptr, nullptr, 3 * DIM);

    // 3. scores = scale*QK^T + bias
    attn_scores<<<dim3(10, 10, BH), 256>>>();

    // 4. softmax rows
    softmax_rows<<<BH * NTOK, 128>>>();

    // 5. O = P @ V  ->  [b][n][h*d]
    attn_pv<<<dim3(10, BH), 256>>>();

    // 6. output projection + bias
    sgemm_nt<1><<<dim3(4, 145), 256>>>(nullptr, proj_w, proj_b, out, DIM);
}

// round 2
// speedup vs baseline: 2.5627x; 2.5627x over previous
#include <cuda_runtime.h>
#include <cstdint>

// ---------------------------------------------------------------------------
// Relative attention — tf32 tensor-core GEMMs + fused flash attention.
// Shapes: x[32,577,512], qkv_w[1536,512], proj_w[512,512], proj_b[512],
//         bias_table[2209,8], rel_index[577,577] (int32), out[32,577,512].
// ---------------------------------------------------------------------------

namespace {
constexpr int BATCH = 32;
constexpr int NH    = 8;
constexpr int NTOK  = 577;
constexpr int DIM   = 512;
constexpr int DH    = 64;
constexpr int BH    = BATCH * NH;        // 256
constexpr int MROWS = BATCH * NTOK;      // 18464
constexpr int NN    = NTOK * NTOK;       // 332929
constexpr float SCALE = 0.125f;
constexpr float LOG2E = 1.4426950408889634f;
}

// Scratch (device globals: allocation-free contract)
__device__ float g_q[BH * NTOK * DH];
__device__ float g_k[BH * NTOK * DH];
__device__ float g_v[BH * NTOK * DH];
__device__ float g_bias[NH * NN];
__device__ float g_attn[MROWS * DIM];

// ---------------------------------------------------------------------------
__device__ __forceinline__ float to_tf32(float x) {
    unsigned u;
    asm("cvt.rna.tf32.f32 %0, %1;" : "=r"(u) : "f"(x));
    return __uint_as_float(u);
}

__device__ __forceinline__ void mma8(float* d, const float* a, const float* b) {
    asm volatile(
        "mma.sync.aligned.m16n8k8.row.col.f32.tf32.tf32.f32 "
        "{%0,%1,%2,%3},{%4,%5,%6,%7},{%8,%9},{%0,%1,%2,%3};"
        : "+f"(d[0]), "+f"(d[1]), "+f"(d[2]), "+f"(d[3])
        : "r"(__float_as_uint(a[0])), "r"(__float_as_uint(a[1])),
          "r"(__float_as_uint(a[2])), "r"(__float_as_uint(a[3])),
          "r"(__float_as_uint(b[0])), "r"(__float_as_uint(b[1])));
}

// ---------------------------------------------------------------------------
// Bias gather: g_bias[h][n][m] = table[rel[n][m]][h]
// ---------------------------------------------------------------------------
__global__ void bias_expand(const float* __restrict__ table,
                            const int* __restrict__ rel) {
    int idx = blockIdx.x * 256 + threadIdx.x;
    if (idx >= NN) return;
    int r = rel[idx];
#pragma unroll
    for (int h = 0; h < NH; ++h)
        g_bias[h * NN + idx] = table[r * NH + h];
}

// ---------------------------------------------------------------------------
// tf32 NT GEMM: C[m,n] = sum_k A[m,k]*B[n,k]. 128x128x32 tile, 8 warps.
// MODE 0: A=x, B=qkv_w, scatter into g_q/g_k/g_v.  MODE 1: A=g_attn, B=proj_w.
// ---------------------------------------------------------------------------
template <int MODE>
__global__ __launch_bounds__(256) void gemm_tf32(const float* __restrict__ Ain,
                                                 const float* __restrict__ Bm,
                                                 const float* __restrict__ bias,
                                                 float* __restrict__ Cout,
                                                 int Ntot) {
    const float* A = (MODE == 1) ? g_attn : Ain;
    __shared__ float As[128][36];   // stride 36: 4g+t bank pattern conflict-free
    __shared__ float Bs[128][36];
    const int tid = threadIdx.x;
    const int lane = tid & 31, wid = tid >> 5;
    const int g = lane >> 2, t = lane & 3;
    const int m0 = blockIdx.y * 128, n0 = blockIdx.x * 128;
    const int wm = (wid >> 2) * 64, wn = (wid & 3) * 32;

    float acc[4][4][4];
#pragma unroll
    for (int i = 0; i < 4; ++i)
#pragma unroll
        for (int j = 0; j < 4; ++j)
#pragma unroll
            for (int e = 0; e < 4; ++e) acc[i][j][e] = 0.f;

    for (int k0 = 0; k0 < DIM; k0 += 32) {
#pragma unroll
        for (int it = 0; it < 4; ++it) {
            int s = tid + it * 256;
            int row = s >> 3, c4 = (s & 7) << 2;
            float4 va = make_float4(0.f, 0.f, 0.f, 0.f);
            if (m0 + row < MROWS)
                va = *reinterpret_cast<const float4*>(A + (size_t)(m0 + row) * DIM + k0 + c4);
            float4 ta = make_float4(to_tf32(va.x), to_tf32(va.y), to_tf32(va.z), to_tf32(va.w));
            *reinterpret_cast<float4*>(&As[row][c4]) = ta;
            float4 vb = make_float4(0.f, 0.f, 0.f, 0.f);
            if (n0 + row < Ntot)
                vb = *reinterpret_cast<const float4*>(Bm + (size_t)(n0 + row) * DIM + k0 + c4);
            float4 tb = make_float4(to_tf32(vb.x), to_tf32(vb.y), to_tf32(vb.z), to_tf32(vb.w));
            *reinterpret_cast<float4*>(&Bs[row][c4]) = tb;
        }
        __syncthreads();
#pragma unroll
        for (int ks = 0; ks < 4; ++ks) {
            const int kd = ks * 8;
            float a[4][4];
#pragma unroll
            for (int mf = 0; mf < 4; ++mf) {
                int mr = wm + mf * 16;
                a[mf][0] = As[mr + g][kd + t];
                a[mf][1] = As[mr + g + 8][kd + t];
                a[mf][2] = As[mr + g][kd + t + 4];
                a[mf][3] = As[mr + g + 8][kd + t + 4];
            }
#pragma unroll
            for (int nf = 0; nf < 4; ++nf) {
                int nr = wn + nf * 8;
                float b[2] = {Bs[nr + g][kd + t], Bs[nr + g][kd + t + 4]};
#pragma unroll
                for (int mf = 0; mf < 4; ++mf) mma8(acc[mf][nf], a[mf], b);
            }
        }
        __syncthreads();
    }

    if (MODE == 0) {
#pragma unroll
        for (int mf = 0; mf < 4; ++mf) {
#pragma unroll
            for (int ri = 0; ri < 2; ++ri) {
                int gm = m0 + wm + mf * 16 + g + ri * 8;
                if (gm >= MROWS) continue;
                int b_ = gm / NTOK;
                int n_ = gm - b_ * NTOK;
#pragma unroll
                for (int nf = 0; nf < 4; ++nf) {
#pragma unroll
                    for (int ci = 0; ci < 2; ++ci) {
                        int gn = n0 + wn + nf * 8 + t * 2 + ci;
                        int part = gn >> 9;
                        int rem = gn & 511;
                        int h_ = rem >> 6;
                        int dd = rem & 63;
                        float* dst = (part == 0) ? g_q : (part == 1) ? g_k : g_v;
                        dst[((b_ * NH + h_) * NTOK + n_) * DH + dd] = acc[mf][nf][ri * 2 + ci];
                    }
                }
            }
        }
    } else {
#pragma unroll
        for (int mf = 0; mf < 4; ++mf) {
#pragma unroll
            for (int ri = 0; ri < 2; ++ri) {
                int gm = m0 + wm + mf * 16 + g + ri * 8;
                if (gm >= MROWS) continue;
#pragma unroll
                for (int nf = 0; nf < 4; ++nf) {
                    int cbase = n0 + wn + nf * 8 + t * 2;
                    float2 o;
                    o.x = acc[mf][nf][ri * 2 + 0] + bias[cbase];
                    o.y = acc[mf][nf][ri * 2 + 1] + bias[cbase + 1];
                    *reinterpret_cast<float2*>(Cout + (size_t)gm * DIM + cbase) = o;
                }
            }
        }
    }
}

// ---------------------------------------------------------------------------
// Fused flash attention with relative-position bias.
// Block: 256 thr (8 warps), 128 q-rows; streams 64-key tiles (10 tiles).
// Dynamic smem: Qs[128][68], Ps[128][68], Bb[128][68], Ks[64][68], Vs[64][72].
// ---------------------------------------------------------------------------
namespace {
constexpr int QS_OFF = 0;
constexpr int PS_OFF = QS_OFF + 128 * 68;
constexpr int BB_OFF = PS_OFF + 128 * 68;
constexpr int KS_OFF = BB_OFF + 128 * 68;
constexpr int VS_OFF = KS_OFF + 64 * 68;
constexpr int SMEM_FLOATS = VS_OFF + 64 * 72;     // 35072 floats = 140288 B
}

__global__ __launch_bounds__(256) void flash_attn() {
    extern __shared__ float sm[];
    float (*Qs)[68] = reinterpret_cast<float(*)[68]>(sm + QS_OFF);
    float (*Ps)[68] = reinterpret_cast<float(*)[68]>(sm + PS_OFF);
    float (*Bb)[68] = reinterpret_cast<float(*)[68]>(sm + BB_OFF);
    float (*Ks)[68] = reinterpret_cast<float(*)[68]>(sm + KS_OFF);
    float (*Vs)[72] = reinterpret_cast<float(*)[72]>(sm + VS_OFF);

    const int bh = blockIdx.y, qt = blockIdx.x;
    const int tid = threadIdx.x;
    const int wid = tid >> 5, lane = tid & 31;
    const int g = lane >> 2, t = lane & 3;
    const float* qb = g_q + (size_t)bh * NTOK * DH;
    const float* kb = g_k + (size_t)bh * NTOK * DH;
    const float* vb = g_v + (size_t)bh * NTOK * DH;
    const float* brow = g_bias + (size_t)(bh & 7) * NN;

    // load Q tile (128 x 64), converted to tf32
#pragma unroll
    for (int it = 0; it < 8; ++it) {
        int s = tid + it * 256;
        int row = s >> 4, c4 = (s & 15) << 2;
        int gq = qt * 128 + row;
        float4 v = make_float4(0.f, 0.f, 0.f, 0.f);
        if (gq < NTOK) v = *reinterpret_cast<const float4*>(qb + (size_t)gq * DH + c4);
        float4 tv = make_float4(to_tf32(v.x), to_tf32(v.y), to_tf32(v.z), to_tf32(v.w));
        *reinterpret_cast<float4*>(&Qs[row][c4]) = tv;
    }

    const int q0 = wid * 16;
    const int rowA = qt * 128 + q0 + g;
    const int rowB = rowA + 8;

    float accO[8][4];
#pragma unroll
    for (int df = 0; df < 8; ++df)
#pragma unroll
        for (int e = 0; e < 4; ++e) accO[df][e] = 0.f;
    float m_a = -1e30f, m_b = -1e30f, sum_a = 0.f, sum_b = 0.f;

    for (int kt = 0; kt < 10; ++kt) {
        const int k0 = kt * 64;
        // K, V tiles (64 x 64)
#pragma unroll
        for (int it = 0; it < 4; ++it) {
            int s = tid + it * 256;
            int row = s >> 4, c4 = (s & 15) << 2;
            int gk = k0 + row;
            float4 kv = make_float4(0.f, 0.f, 0.f, 0.f);
            float4 vv = make_float4(0.f, 0.f, 0.f, 0.f);
            if (gk < NTOK) {
                kv = *reinterpret_cast<const float4*>(kb + (size_t)gk * DH + c4);
                vv = *reinterpret_cast<const float4*>(vb + (size_t)gk * DH + c4);
            }
            float4 tk = make_float4(to_tf32(kv.x), to_tf32(kv.y), to_tf32(kv.z), to_tf32(kv.w));
            *reinterpret_cast<float4*>(&Ks[row][c4]) = tk;
            float4 tv = make_float4(to_tf32(vv.x), to_tf32(vv.y), to_tf32(vv.z), to_tf32(vv.w));
            *reinterpret_cast<float4*>(&Vs[row][c4]) = tv;
        }
        // bias tile (128 x 64), coalesced scalar loads
#pragma unroll
        for (int i = 0; i < 32; ++i) {
            int idx = i * 256 + tid;
            int row = idx >> 6, col = idx & 63;
            int gq = qt * 128 + row, gk = k0 + col;
            Bb[row][col] = (gq < NTOK && gk < NTOK)
                               ? brow[(size_t)gq * NTOK + gk] : -1e30f;
        }
        __syncthreads();

        // S = Q K^T (per warp: 16 x 64)
        float S[8][4];
#pragma unroll
        for (int nf = 0; nf < 8; ++nf)
#pragma unroll
            for (int e = 0; e < 4; ++e) S[nf][e] = 0.f;
#pragma unroll
        for (int ks = 0; ks < 8; ++ks) {
            const int kd = ks * 8;
            float a[4] = {Qs[q0 + g][kd + t], Qs[q0 + g + 8][kd + t],
                          Qs[q0 + g][kd + t + 4], Qs[q0 + g + 8][kd + t + 4]};
#pragma unroll
            for (int nf = 0; nf < 8; ++nf) {
                float b[2] = {Ks[nf * 8 + g][kd + t], Ks[nf * 8 + g][kd + t + 4]};
                mma8(S[nf], a, b);
            }
        }

        // scale + bias, row max
        float ma = -1e30f, mb = -1e30f;
#pragma unroll
        for (int nf = 0; nf < 8; ++nf) {
            int c = nf * 8 + t * 2;
            S[nf][0] = S[nf][0] * SCALE + Bb[q0 + g][c];
            S[nf][1] = S[nf][1] * SCALE + Bb[q0 + g][c + 1];
            S[nf][2] = S[nf][2] * SCALE + Bb[q0 + g + 8][c];
            S[nf][3] = S[nf][3] * SCALE + Bb[q0 + g + 8][c + 1];
            ma = fmaxf(ma, fmaxf(S[nf][0], S[nf][1]));
            mb = fmaxf(mb, fmaxf(S[nf][2], S[nf][3]));
        }
        ma = fmaxf(ma, __shfl_xor_sync(0xFFFFFFFFu, ma, 1));
        ma = fmaxf(ma, __shfl_xor_sync(0xFFFFFFFFu, ma, 2));
        mb = fmaxf(mb, __shfl_xor_sync(0xFFFFFFFFu, mb, 1));
        mb = fmaxf(mb, __shfl_xor_sync(0xFFFFFFFFu, mb, 2));

        float mna = fmaxf(m_a, ma), mnb = fmaxf(m_b, mb);
        float alA = exp2f((m_a - mna) * LOG2E);
        float alB = exp2f((m_b - mnb) * LOG2E);
        m_a = mna; m_b = mnb;

        float pa = 0.f, pb = 0.f;
#pragma unroll
        for (int nf = 0; nf < 8; ++nf) {
            int c = nf * 8 + t * 2;
            S[nf][0] = exp2f((S[nf][0] - mna) * LOG2E);
            S[nf][1] = exp2f((S[nf][1] - mna) * LOG2E);
            S[nf][2] = exp2f((S[nf][2] - mnb) * LOG2E);
            S[nf][3] = exp2f((S[nf][3] - mnb) * LOG2E);
            pa += S[nf][0] + S[nf][1];
            pb += S[nf][2] + S[nf][3];
            Ps[q0 + g][c]         = to_tf32(S[nf][0]);
            Ps[q0 + g][c + 1]     = to_tf32(S[nf][1]);
            Ps[q0 + g + 8][c]     = to_tf32(S[nf][2]);
            Ps[q0 + g + 8][c + 1] = to_tf32(S[nf][3]);
        }
        sum_a = sum_a * alA + pa;
        sum_b = sum_b * alB + pb;
#pragma unroll
        for (int df = 0; df < 8; ++df) {
            accO[df][0] *= alA; accO[df][1] *= alA;
            accO[df][2] *= alB; accO[df][3] *= alB;
        }
        __syncwarp();

        // O += P V
#pragma unroll
        for (int ks = 0; ks < 8; ++ks) {
            const int kd = ks * 8;
            float a[4] = {Ps[q0 + g][kd + t], Ps[q0 + g + 8][kd + t],
                          Ps[q0 + g][kd + t + 4], Ps[q0 + g + 8][kd + t + 4]};
#pragma unroll
            for (int df = 0; df < 8; ++df) {
                float b[2] = {Vs[kd + t][df * 8 + g], Vs[kd + t + 4][df * 8 + g]};
                mma8(accO[df], a, b);
            }
        }
        __syncthreads();
    }

    sum_a += __shfl_xor_sync(0xFFFFFFFFu, sum_a, 1);
    sum_a += __shfl_xor_sync(0xFFFFFFFFu, sum_a, 2);
    sum_b += __shfl_xor_sync(0xFFFFFFFFu, sum_b, 1);
    sum_b += __shfl_xor_sync(0xFFFFFFFFu, sum_b, 2);
    const float ia = 1.f / sum_a, ib = 1.f / sum_b;

    const int b_ = bh >> 3, h_ = bh & 7;
#pragma unroll
    for (int df = 0; df < 8; ++df) {
        int col = h_ * 64 + df * 8 + t * 2;
        if (rowA < NTOK) {
            float2 o = make_float2(accO[df][0] * ia, accO[df][1] * ia);
            *reinterpret_cast<float2*>(&g_attn[(size_t)(b_ * NTOK + rowA) * DIM + col]) = o;
        }
        if (rowB < NTOK) {
            float2 o = make_float2(accO[df][2] * ib, accO[df][3] * ib);
            *reinterpret_cast<float2*>(&g_attn[(size_t)(b_ * NTOK + rowB) * DIM + col]) = o;
        }
    }
}

// ---------------------------------------------------------------------------
extern "C" void kernel_launch(void* const* d_in, const int* in_sizes, int n_in,
                              void* d_out, int out_size) {
    (void)in_sizes; (void)n_in; (void)out_size;
    const float* x          = (const float*)d_in[0];
    const float* qkv_w      = (const float*)d_in[1];
    const float* proj_w     = (const float*)d_in[2];
    const float* proj_b     = (const float*)d_in[3];
    const float* bias_table = (const float*)d_in[4];
    const int*   rel_index  = (const int*)d_in[5];
    float* out = (float*)d_out;

    cudaFuncSetAttribute(flash_attn, cudaFuncAttributeMaxDynamicSharedMemorySize,
                         SMEM_FLOATS * sizeof(float));

    bias_expand<<<(NN + 255) / 256, 256>>>(bias_table, rel_index);
    gemm_tf32<0><<<dim3(12, 145), 256>>>(x, qkv_w, nullptr, nullptr, 3 * DIM);
    flash_attn<<<dim3(5, BH), 256, SMEM_FLOATS * sizeof(float)>>>();
    gemm_tf32<1><<<dim3(4, 145), 256>>>(nullptr, proj_w, proj_b, out, DIM);
}

// round 3
// speedup vs baseline: 3.3954x; 1.3249x over previous
#include <cuda_runtime.h>
#include <cstdint>

// ---------------------------------------------------------------------------
// Relative attention — tf32 mma GEMMs (cp.async double-buffered) + fused
// flash attention with pipelined K/V/bias loads.
// ---------------------------------------------------------------------------

namespace {
constexpr int BATCH = 32;
constexpr int NH    = 8;
constexpr int NTOK  = 577;
constexpr int DIM   = 512;
constexpr int DH    = 64;
constexpr int BH    = BATCH * NH;        // 256
constexpr int MROWS = BATCH * NTOK;      // 18464
constexpr int BPAD  = 640;               // padded bias row stride
constexpr float SCALE = 0.125f;
constexpr float LOG2E = 1.4426950408889634f;
}

// Scratch (device globals: allocation-free contract)
__device__ float g_q[BH * NTOK * DH];
__device__ float g_k[BH * NTOK * DH];
__device__ float g_v[BH * NTOK * DH];
__device__ float g_biasp[NH * NTOK * BPAD];     // 11.8 MB, cols>=577 = -1e30
__device__ float g_attn[MROWS * DIM];

// ---------------------------------------------------------------------------
__device__ __forceinline__ float to_tf32(float x) {
    unsigned u;
    asm("cvt.rna.tf32.f32 %0, %1;" : "=r"(u) : "f"(x));
    return __uint_as_float(u);
}

__device__ __forceinline__ void mma8(float* d, const float* a, const float* b) {
    asm volatile(
        "mma.sync.aligned.m16n8k8.row.col.f32.tf32.tf32.f32 "
        "{%0,%1,%2,%3},{%4,%5,%6,%7},{%8,%9},{%0,%1,%2,%3};"
        : "+f"(d[0]), "+f"(d[1]), "+f"(d[2]), "+f"(d[3])
        : "r"(__float_as_uint(a[0])), "r"(__float_as_uint(a[1])),
          "r"(__float_as_uint(a[2])), "r"(__float_as_uint(a[3])),
          "r"(__float_as_uint(b[0])), "r"(__float_as_uint(b[1])));
}

__device__ __forceinline__ void cp16(float* dst, const float* src) {
    unsigned d = (unsigned)__cvta_generic_to_shared(dst);
    asm volatile("cp.async.cg.shared.global [%0], [%1], 16;\n" :: "r"(d), "l"(src));
}
__device__ __forceinline__ void cp_commit() {
    asm volatile("cp.async.commit_group;\n" ::);
}
template <int N>
__device__ __forceinline__ void cp_wait() {
    asm volatile("cp.async.wait_group %0;\n" :: "n"(N));
}

// ---------------------------------------------------------------------------
// Bias expand: g_biasp[h][n][c] = table[rel[n][c]][h] for c<577, else -1e30.
// ---------------------------------------------------------------------------
__global__ void bias_expand(const float* __restrict__ table,
                            const int* __restrict__ rel) {
    int idx = blockIdx.x * 256 + threadIdx.x;
    if (idx >= NTOK * BPAD) return;
    int n = idx / BPAD, c = idx - n * BPAD;
    if (c < NTOK) {
        int r = rel[n * NTOK + c];
#pragma unroll
        for (int h = 0; h < NH; ++h)
            g_biasp[((size_t)h * NTOK + n) * BPAD + c] = table[r * NH + h];
    } else {
#pragma unroll
        for (int h = 0; h < NH; ++h)
            g_biasp[((size_t)h * NTOK + n) * BPAD + c] = -1e30f;
    }
}

// ---------------------------------------------------------------------------
// tf32 NT GEMM, 128x128x32 tile, cp.async double-buffered, 2 blocks/SM.
// MODE 0: A=x, B=qkv_w, scatter into g_q/g_k/g_v.  MODE 1: A=g_attn, B=proj_w.
// ---------------------------------------------------------------------------
namespace {
constexpr int GSTAGE = 2 * 128 * 36;                 // floats per stage (A+B)
constexpr int GEMM_SMEM = 2 * GSTAGE * 4;            // 73728 bytes
}

template <int MODE>
__global__ __launch_bounds__(256, 2) void gemm_tf32(const float* __restrict__ Ain,
                                                    const float* __restrict__ Bm,
                                                    const float* __restrict__ bias,
                                                    float* __restrict__ Cout) {
    extern __shared__ float smg[];
    const float* A = (MODE == 1) ? g_attn : Ain;
    const int tid = threadIdx.x;
    const int lane = tid & 31, wid = tid >> 5;
    const int g = lane >> 2, t = lane & 3;
    const int m0 = blockIdx.y * 128, n0 = blockIdx.x * 128;
    const int wm = (wid >> 2) * 64, wn = (wid & 3) * 32;

    float acc[4][4][4];
#pragma unroll
    for (int i = 0; i < 4; ++i)
#pragma unroll
        for (int j = 0; j < 4; ++j)
#pragma unroll
            for (int e = 0; e < 4; ++e) acc[i][j][e] = 0.f;

    auto issue = [&](int st, int k0) {
        float* As = smg + st * GSTAGE;
        float* Bs = As + 128 * 36;
#pragma unroll
        for (int it = 0; it < 4; ++it) {
            int v = tid + it * 256;
            int row = v >> 3, c4 = (v & 7) << 2;
            int gm = m0 + row; if (gm > MROWS - 1) gm = MROWS - 1;
            cp16(&As[row * 36 + c4], A + (size_t)gm * DIM + k0 + c4);
            int gn = n0 + row;    // grids exact in N: no clamp needed
            cp16(&Bs[row * 36 + c4], Bm + (size_t)gn * DIM + k0 + c4);
        }
        cp_commit();
    };

    issue(0, 0);
    for (int k0 = 0; k0 < DIM; k0 += 32) {
        const int st = (k0 >> 5) & 1;
        if (k0 + 32 < DIM) { issue(st ^ 1, k0 + 32); cp_wait<1>(); }
        else cp_wait<0>();
        __syncthreads();

        const float* As = smg + st * GSTAGE;
        const float* Bs = As + 128 * 36;
#pragma unroll
        for (int ks = 0; ks < 4; ++ks) {
            const int kd = ks * 8;
            float a[4][4];
#pragma unroll
            for (int mf = 0; mf < 4; ++mf) {
                int mr = wm + mf * 16;
                a[mf][0] = to_tf32(As[(mr + g) * 36 + kd + t]);
                a[mf][1] = to_tf32(As[(mr + g + 8) * 36 + kd + t]);
                a[mf][2] = to_tf32(As[(mr + g) * 36 + kd + t + 4]);
                a[mf][3] = to_tf32(As[(mr + g + 8) * 36 + kd + t + 4]);
            }
#pragma unroll
            for (int nf = 0; nf < 4; ++nf) {
                int nr = wn + nf * 8;
                float b[2] = {to_tf32(Bs[(nr + g) * 36 + kd + t]),
                              to_tf32(Bs[(nr + g) * 36 + kd + t + 4])};
#pragma unroll
                for (int mf = 0; mf < 4; ++mf) mma8(acc[mf][nf], a[mf], b);
            }
        }
        __syncthreads();
    }

    if (MODE == 0) {
#pragma unroll
        for (int mf = 0; mf < 4; ++mf) {
#pragma unroll
            for (int ri = 0; ri < 2; ++ri) {
                int gm = m0 + wm + mf * 16 + g + ri * 8;
                if (gm >= MROWS) continue;
                int b_ = gm / NTOK;
                int n_ = gm - b_ * NTOK;
#pragma unroll
                for (int nf = 0; nf < 4; ++nf) {
#pragma unroll
                    for (int ci = 0; ci < 2; ++ci) {
                        int gn = n0 + wn + nf * 8 + t * 2 + ci;
                        int part = gn >> 9;
                        int rem = gn & 511;
                        int h_ = rem >> 6;
                        int dd = rem & 63;
                        float* dst = (part == 0) ? g_q : (part == 1) ? g_k : g_v;
                        dst[((b_ * NH + h_) * NTOK + n_) * DH + dd] = acc[mf][nf][ri * 2 + ci];
                    }
                }
            }
        }
    } else {
#pragma unroll
        for (int mf = 0; mf < 4; ++mf) {
#pragma unroll
            for (int ri = 0; ri < 2; ++ri) {
                int gm = m0 + wm + mf * 16 + g + ri * 8;
                if (gm >= MROWS) continue;
#pragma unroll
                for (int nf = 0; nf < 4; ++nf) {
                    int cbase = n0 + wn + nf * 8 + t * 2;
                    float2 o;
                    o.x = acc[mf][nf][ri * 2 + 0] + bias[cbase];
                    o.y = acc[mf][nf][ri * 2 + 1] + bias[cbase + 1];
                    *reinterpret_cast<float2*>(Cout + (size_t)gm * DIM + cbase) = o;
                }
            }
        }
    }
}

// ---------------------------------------------------------------------------
// Fused flash attention. 256 thr / 128 q-rows per block, 64-key tiles.
// K/V double-buffered cp.async; bias cp.async waited only at epilogue.
// ---------------------------------------------------------------------------
namespace {
constexpr int QS_OFF = 0;                         // Qs[128][68] (tf32)
constexpr int PS_OFF = QS_OFF + 128 * 68;         // Ps[128][68] (tf32)
constexpr int BB_OFF = PS_OFF + 128 * 68;         // Bb[128][68]
constexpr int KS_OFF = BB_OFF + 128 * 68;         // Ks[2][64][68] (raw fp32)
constexpr int VS_OFF = KS_OFF + 2 * 64 * 68;      // Vs[2][64][72] (raw fp32)
constexpr int FL_SMEM = (VS_OFF + 2 * 64 * 72) * 4;   // 176128 bytes
}

__global__ __launch_bounds__(256) void flash_attn() {
    extern __shared__ float sm[];
    float (*Qs)[68] = reinterpret_cast<float(*)[68]>(sm + QS_OFF);
    float (*Ps)[68] = reinterpret_cast<float(*)[68]>(sm + PS_OFF);
    float (*Bb)[68] = reinterpret_cast<float(*)[68]>(sm + BB_OFF);

    const int bh = blockIdx.y, qt = blockIdx.x;
    const int tid = threadIdx.x;
    const int wid = tid >> 5, lane = tid & 31;
    const int g = lane >> 2, t = lane & 3;
    const float* qb = g_q + (size_t)bh * NTOK * DH;
    const float* kb = g_k + (size_t)bh * NTOK * DH;
    const float* vb = g_v + (size_t)bh * NTOK * DH;
    const float* bp = g_biasp + (size_t)(bh & 7) * NTOK * BPAD;

    auto issueKV = [&](int st, int k0) {
        float* Ks = sm + KS_OFF + st * 64 * 68;
        float* Vs = sm + VS_OFF + st * 64 * 72;
#pragma unroll
        for (int it = 0; it < 4; ++it) {
            int v = tid + it * 256;
            int row = v >> 4, c4 = (v & 15) << 2;
            int gk = k0 + row; if (gk > NTOK - 1) gk = NTOK - 1;   // bias pad masks
            cp16(&Ks[row * 68 + c4], kb + (size_t)gk * DH + c4);
            cp16(&Vs[row * 72 + c4], vb + (size_t)gk * DH + c4);
        }
        cp_commit();
    };

    // prologue: start KV(0); load+convert Q tile
    issueKV(0, 0);
#pragma unroll
    for (int it = 0; it < 8; ++it) {
        int s = tid + it * 256;
        int row = s >> 4, c4 = (s & 15) << 2;
        int gq = qt * 128 + row; if (gq > NTOK - 1) gq = NTOK - 1;
        float4 v = *reinterpret_cast<const float4*>(qb + (size_t)gq * DH + c4);
        float4 tv = make_float4(to_tf32(v.x), to_tf32(v.y), to_tf32(v.z), to_tf32(v.w));
        *reinterpret_cast<float4*>(&Qs[row][c4]) = tv;
    }

    const int q0 = wid * 16;
    const int rowA = qt * 128 + q0 + g;
    const int rowB = rowA + 8;

    float accO[8][4];
#pragma unroll
    for (int df = 0; df < 8; ++df)
#pragma unroll
        for (int e = 0; e < 4; ++e) accO[df][e] = 0.f;
    float m_a = -1e30f, m_b = -1e30f, sum_a = 0.f, sum_b = 0.f;

    for (int kt = 0; kt < 10; ++kt) {
        const int k0 = kt * 64;
        const int st = kt & 1;
        const float* Ks = sm + KS_OFF + st * 64 * 68;
        const float* Vs = sm + VS_OFF + st * 64 * 72;

        // issue bias(kt) then KV(kt+1); groups: [.., B_kt, KV_{kt+1}]
#pragma unroll
        for (int it = 0; it < 8; ++it) {
            int v = tid + it * 256;
            int row = v >> 4, c4 = (v & 15) << 2;
            int gq = qt * 128 + row; if (gq > NTOK - 1) gq = NTOK - 1;
            cp16(&Bb[row][c4], bp + (size_t)gq * BPAD + k0 + c4);
        }
        cp_commit();
        if (kt < 9) issueKV(st ^ 1, k0 + 64);

        if (kt < 9) cp_wait<2>(); else cp_wait<1>();   // KV(kt) ready
        __syncthreads();

        // S = Q K^T
        float S[8][4];
#pragma unroll
        for (int nf = 0; nf < 8; ++nf)
#pragma unroll
            for (int e = 0; e < 4; ++e) S[nf][e] = 0.f;
#pragma unroll
        for (int ks = 0; ks < 8; ++ks) {
            const int kd = ks * 8;
            float a[4] = {Qs[q0 + g][kd + t], Qs[q0 + g + 8][kd + t],
                          Qs[q0 + g][kd + t + 4], Qs[q0 + g + 8][kd + t + 4]};
#pragma unroll
            for (int nf = 0; nf < 8; ++nf) {
                float b[2] = {to_tf32(Ks[(nf * 8 + g) * 68 + kd + t]),
                              to_tf32(Ks[(nf * 8 + g) * 68 + kd + t + 4])};
                mma8(S[nf], a, b);
            }
        }

        if (kt < 9) cp_wait<1>(); else cp_wait<0>();   // bias(kt) ready
        __syncthreads();

        // scale + bias + online softmax
        float ma = -1e30f, mb = -1e30f;
#pragma unroll
        for (int nf = 0; nf < 8; ++nf) {
            int c = nf * 8 + t * 2;
            float2 bA = *reinterpret_cast<const float2*>(&Bb[q0 + g][c]);
            float2 bB = *reinterpret_cast<const float2*>(&Bb[q0 + g + 8][c]);
            S[nf][0] = S[nf][0] * SCALE + bA.x;
            S[nf][1] = S[nf][1] * SCALE + bA.y;
            S[nf][2] = S[nf][2] * SCALE + bB.x;
            S[nf][3] = S[nf][3] * SCALE + bB.y;
            ma = fmaxf(ma, fmaxf(S[nf][0], S[nf][1]));
            mb = fmaxf(mb, fmaxf(S[nf][2], S[nf][3]));
        }
        ma = fmaxf(ma, __shfl_xor_sync(0xFFFFFFFFu, ma, 1));
        ma = fmaxf(ma, __shfl_xor_sync(0xFFFFFFFFu, ma, 2));
        mb = fmaxf(mb, __shfl_xor_sync(0xFFFFFFFFu, mb, 1));
        mb = fmaxf(mb, __shfl_xor_sync(0xFFFFFFFFu, mb, 2));

        float mna = fmaxf(m_a, ma), mnb = fmaxf(m_b, mb);
        float alA = exp2f((m_a - mna) * LOG2E);
        float alB = exp2f((m_b - mnb) * LOG2E);
        m_a = mna; m_b = mnb;

        float pa = 0.f, pb = 0.f;
#pragma unroll
        for (int nf = 0; nf < 8; ++nf) {
            int c = nf * 8 + t * 2;
            S[nf][0] = exp2f((S[nf][0] - mna) * LOG2E);
            S[nf][1] = exp2f((S[nf][1] - mna) * LOG2E);
            S[nf][2] = exp2f((S[nf][2] - mnb) * LOG2E);
            S[nf][3] = exp2f((S[nf][3] - mnb) * LOG2E);
            pa += S[nf][0] + S[nf][1];
            pb += S[nf][2] + S[nf][3];
            Ps[q0 + g][c]         = to_tf32(S[nf][0]);
            Ps[q0 + g][c + 1]     = to_tf32(S[nf][1]);
            Ps[q0 + g + 8][c]     = to_tf32(S[nf][2]);
            Ps[q0 + g + 8][c + 1] = to_tf32(S[nf][3]);
        }
        sum_a = sum_a * alA + pa;
        sum_b = sum_b * alB + pb;
#pragma unroll
        for (int df = 0; df < 8; ++df) {
            accO[df][0] *= alA; accO[df][1] *= alA;
            accO[df][2] *= alB; accO[df][3] *= alB;
        }
        __syncwarp();

        // O += P V
#pragma unroll
        for (int ks = 0; ks < 8; ++ks) {
            const int kd = ks * 8;
            float a[4] = {Ps[q0 + g][kd + t], Ps[q0 + g + 8][kd + t],
                          Ps[q0 + g][kd + t + 4], Ps[q0 + g + 8][kd + t + 4]};
#pragma unroll
            for (int df = 0; df < 8; ++df) {
                float b[2] = {to_tf32(Vs[(kd + t) * 72 + df * 8 + g]),
                              to_tf32(Vs[(kd + t + 4) * 72 + df * 8 + g])};
                mma8(accO[df], a, b);
            }
        }
        __syncthreads();
    }

    sum_a += __shfl_xor_sync(0xFFFFFFFFu, sum_a, 1);
    sum_a += __shfl_xor_sync(0xFFFFFFFFu, sum_a, 2);
    sum_b += __shfl_xor_sync(0xFFFFFFFFu, sum_b, 1);
    sum_b += __shfl_xor_sync(0xFFFFFFFFu, sum_b, 2);
    const float ia = 1.f / sum_a, ib = 1.f / sum_b;

    const int b_ = bh >> 3, h_ = bh & 7;
#pragma unroll
    for (int df = 0; df < 8; ++df) {
        int col = h_ * 64 + df * 8 + t * 2;
        if (rowA < NTOK) {
            float2 o = make_float2(accO[df][0] * ia, accO[df][1] * ia);
            *reinterpret_cast<float2*>(&g_attn[(size_t)(b_ * NTOK + rowA) * DIM + col]) = o;
        }
        if (rowB < NTOK) {
            float2 o = make_float2(accO[df][2] * ib, accO[df][3] * ib);
            *reinterpret_cast<float2*>(&g_attn[(size_t)(b_ * NTOK + rowB) * DIM + col]) = o;
        }
    }
}

// ---------------------------------------------------------------------------
extern "C" void kernel_launch(void* const* d_in, const int* in_sizes, int n_in,
                              void* d_out, int out_size) {
    (void)in_sizes; (void)n_in; (void)out_size;
    const float* x          = (const float*)d_in[0];
    const float* qkv_w      = (const float*)d_in[1];
    const float* proj_w     = (const float*)d_in[2];
    const float* proj_b     = (const float*)d_in[3];
    const float* bias_table = (const float*)d_in[4];
    const int*   rel_index  = (const int*)d_in[5];
    float* out = (float*)d_out;

    static bool attr_done = false;
    if (!attr_done) {
        cudaFuncSetAttribute(gemm_tf32<0>, cudaFuncAttributeMaxDynamicSharedMemorySize, GEMM_SMEM);
        cudaFuncSetAttribute(gemm_tf32<1>, cudaFuncAttributeMaxDynamicSharedMemorySize, GEMM_SMEM);
        cudaFuncSetAttribute(flash_attn, cudaFuncAttributeMaxDynamicSharedMemorySize, FL_SMEM);
        attr_done = true;
    }

    bias_expand<<<(NTOK * BPAD + 255) / 256, 256>>>(bias_table, rel_index);
    gemm_tf32<0><<<dim3(12, 145), 256, GEMM_SMEM>>>(x, qkv_w, nullptr, nullptr);
    flash_attn<<<dim3(5, BH), 256, FL_SMEM>>>();
    gemm_tf32<1><<<dim3(4, 145), 256, GEMM_SMEM>>>(nullptr, proj_w, proj_b, out);
}